// round 15
// baseline (speedup 1.0000x reference)
#include <cuda_runtime.h>
#include <cuda_fp16.h>
#include <float.h>
#include <math.h>
#include <cstdint>

#define T_   2048
#define D_   1024
#define H_   704
#define E_   16
#define HS_  1408
#define KSEL 4
#define ROUTE_SCALE_ 2.5446f

// ---------------- static device scratch ----------------
__device__ __half g_poh[(size_t)E_ * T_ * D_];   // routed down-proj (fp16)
__device__ int   g_cnt[E_];
__device__ int   g_etok[E_ * T_];
__device__ int   g_slot[T_ * KSEL];
__device__ float g_wt[T_ * KSEL];

__device__ __half g_xh[(size_t)T_ * D_];
__device__ __half g_w1h[(size_t)E_ * H_ * D_];
__device__ __half g_w3h[(size_t)E_ * H_ * D_];
__device__ __half g_w2h[(size_t)E_ * D_ * H_];
__device__ __half g_ws1h[(size_t)HS_ * D_];
__device__ __half g_ws3h[(size_t)HS_ * D_];
__device__ __half g_ws2h[(size_t)D_ * HS_];
__device__ __half g_hth[(size_t)E_ * T_ * H_];
__device__ __half g_ssh[(size_t)T_ * HS_];

// ---------------- helpers ----------------
__device__ __forceinline__ uint32_t smem_u32(const void* p) {
    uint32_t a;
    asm("{ .reg .u64 t; cvta.to.shared.u64 t, %1; cvt.u32.u64 %0, t; }" : "=r"(a) : "l"(p));
    return a;
}
#define CPA(dst, src) \
    asm volatile("cp.async.cg.shared.global [%0], [%1], 16;" :: "r"(dst), "l"(src))
#define CPC() asm volatile("cp.async.commit_group;" ::: "memory")
#define CPW(n) asm volatile("cp.async.wait_group %0;" :: "n"(n) : "memory")
#define LDSM4(R, addr) \
    asm volatile("ldmatrix.sync.aligned.m8n8.x4.shared.b16 {%0,%1,%2,%3}, [%4];" \
        : "=r"((R)[0]), "=r"((R)[1]), "=r"((R)[2]), "=r"((R)[3]) : "r"(addr))

__device__ __forceinline__ void mma16816(float* c, const uint32_t* a, const uint32_t* b) {
    asm volatile(
        "mma.sync.aligned.m16n8k16.row.col.f32.f16.f16.f32 "
        "{%0,%1,%2,%3}, {%4,%5,%6,%7}, {%8,%9}, {%0,%1,%2,%3};"
        : "+f"(c[0]), "+f"(c[1]), "+f"(c[2]), "+f"(c[3])
        : "r"(a[0]), "r"(a[1]), "r"(a[2]), "r"(a[3]), "r"(b[0]), "r"(b[1]));
}
__device__ __forceinline__ float silu_(float v) { return v / (1.f + expf(-v)); }

// ---------------- conversions ----------------
// x -> fp16 (16 elems/thread; also zeroes g_cnt from block 0)
__global__ void conv_x_kernel(const float* __restrict__ in,
                              __half* __restrict__ hi, size_t n16) {
    if (blockIdx.x == 0 && threadIdx.x < E_) g_cnt[threadIdx.x] = 0;
    size_t i = (size_t)blockIdx.x * blockDim.x + threadIdx.x;
    if (i >= n16) return;
    float4 v[4];
#pragma unroll
    for (int q = 0; q < 4; q++) v[q] = ((const float4*)in)[4 * i + q];
    __half h[16];
#pragma unroll
    for (int q = 0; q < 4; q++) {
        h[4 * q + 0] = __float2half_rn(v[q].x);
        h[4 * q + 1] = __float2half_rn(v[q].y);
        h[4 * q + 2] = __float2half_rn(v[q].z);
        h[4 * q + 3] = __float2half_rn(v[q].w);
    }
    ((uint4*)hi)[2 * i]     = ((uint4*)h)[0];
    ((uint4*)hi)[2 * i + 1] = ((uint4*)h)[1];
}

// weights: three tensors per launch, 32 elems/thread
__global__ void conv_w3_kernel(const float* __restrict__ s0, const float* __restrict__ s1,
                               const float* __restrict__ s2,
                               __half* __restrict__ d0, __half* __restrict__ d1,
                               __half* __restrict__ d2, size_t n32) {
    size_t i = (size_t)blockIdx.x * blockDim.x + threadIdx.x;
    if (i >= n32) return;
    const int w = blockIdx.y;
    const float* in = (w == 0) ? s0 : ((w == 1) ? s1 : s2);
    __half* outp = (w == 0) ? d0 : ((w == 1) ? d1 : d2);
    float4 v[8];
#pragma unroll
    for (int q = 0; q < 8; q++) v[q] = ((const float4*)in)[8 * i + q];
    __half h[32];
#pragma unroll
    for (int q = 0; q < 8; q++) {
        h[4 * q + 0] = __float2half_rn(v[q].x);
        h[4 * q + 1] = __float2half_rn(v[q].y);
        h[4 * q + 2] = __float2half_rn(v[q].z);
        h[4 * q + 3] = __float2half_rn(v[q].w);
    }
#pragma unroll
    for (int q = 0; q < 4; q++)
        ((uint4*)outp)[4 * i + q] = ((uint4*)h)[q];
}

// ---------------- gate: gw in smem, split-D (2 warps per token) ----------------
// 256 blocks x 512 threads; 8 tokens/block; warp pair (2t, 2t+1) handles token t.
#define GATE_SMEM (E_ * D_ * 4 + 16 * E_ * 4)   // 64 KB gw + partials

__global__ __launch_bounds__(512) void gate_kernel(const float* __restrict__ x,
                                                   const float* __restrict__ gw,
                                                   const float* __restrict__ gb) {
    extern __shared__ float gws[];               // [E_][D_] then part[16][E_]
    float* part = gws + E_ * D_;
    const int tid = threadIdx.x;
    for (int i = tid; i < E_ * D_ / 4; i += 512)
        ((float4*)gws)[i] = ((const float4*)gw)[i];
    __syncthreads();

    const int warp = tid >> 5, lane = tid & 31;
    const int tok = warp >> 1;        // 0..7
    const int half = warp & 1;        // 0..1
    const int t = blockIdx.x * 8 + tok;
    const float4* xr = (const float4*)(x + (size_t)t * D_);
    float acc[E_];
#pragma unroll
    for (int e = 0; e < E_; e++) acc[e] = 0.f;
    // half covers 128 float4 (4 iterations)
#pragma unroll
    for (int it = 0; it < 4; it++) {
        const int i = half * 128 + it * 32 + lane;
        float4 xv = xr[i];
#pragma unroll
        for (int e = 0; e < E_; e++) {
            float4 g = ((const float4*)(gws + e * D_))[i];
            acc[e] += xv.x * g.x + xv.y * g.y + xv.z * g.z + xv.w * g.w;
        }
    }
#pragma unroll
    for (int e = 0; e < E_; e++) {
#pragma unroll
        for (int o = 16; o; o >>= 1)
            acc[e] += __shfl_xor_sync(0xffffffffu, acc[e], o);
    }
    if (lane < E_) part[warp * E_ + lane] = acc[lane];   // lane e writes acc[e]? no:
    // NOTE: acc[e] identical across lanes after reduce; lane l stores acc[l].
    __syncthreads();

    if (half == 0 && lane == 0) {
        float lg[E_];
#pragma unroll
        for (int e = 0; e < E_; e++)
            lg[e] = part[(2 * tok) * E_ + e] + part[(2 * tok + 1) * E_ + e];
        float sc[E_], r[E_];
#pragma unroll
        for (int e = 0; e < E_; e++) {
            sc[e] = 1.f / (1.f + expf(-lg[e]));
            r[e]  = sc[e] + gb[e];
        }
        float gs[4];
#pragma unroll
        for (int g = 0; g < 4; g++) {
            float m1 = -FLT_MAX, m2 = -FLT_MAX;
#pragma unroll
            for (int j = 0; j < 4; j++) {
                float v = r[4 * g + j];
                if (v > m1) { m2 = m1; m1 = v; }
                else if (v > m2) { m2 = v; }
            }
            gs[g] = m1 + m2;
        }
        int g1 = 0;
#pragma unroll
        for (int g = 1; g < 4; g++) if (gs[g] > gs[g1]) g1 = g;
        int g2 = -1;
#pragma unroll
        for (int g = 0; g < 4; g++) {
            if (g == g1) continue;
            if (g2 < 0 || gs[g] > gs[g2]) g2 = g;
        }
#pragma unroll
        for (int e = 0; e < E_; e++) {
            int g = e >> 2;
            if (g != g1 && g != g2) r[e] = -FLT_MAX;
        }
        int idx[KSEL];
        float wsum = 0.f;
#pragma unroll
        for (int k = 0; k < KSEL; k++) {
            int b = 0; float bv = -FLT_MAX;
#pragma unroll
            for (int e = 0; e < E_; e++)
                if (r[e] > bv) { bv = r[e]; b = e; }
            idx[k] = b;
            r[b] = -FLT_MAX;
            wsum += sc[b];
        }
        wsum = fmaxf(wsum, 1e-9f);
#pragma unroll
        for (int k = 0; k < KSEL; k++) {
            int e = idx[k];
            float wk = sc[e] / wsum * ROUTE_SCALE_;
            int pos = atomicAdd(&g_cnt[e], 1);
            g_etok[e * T_ + pos] = t;
            g_slot[t * KSEL + k] = e * T_ + pos;
            g_wt[t * KSEL + k]   = wk;
        }
    }
}

// ================= phase 1: dual GEMM (gate & up) + SwiGLU, fp16, k64 ==========
#define PITCH 144
#define P1_AM (128 * PITCH)             // 18432
#define P1_BM (64 * PITCH)              // 9216
#define P1_STG (P1_AM + 2 * P1_BM)      // 36864
#define P1_SMEM (2 * P1_STG)            // 73728

__global__ __launch_bounds__(256, 2) void gemm_gu() {
    const int z = blockIdx.z;
    const bool sh = (z >= E_);
    const int xt = sh ? ((z - E_) * 11 + blockIdx.x) : blockIdx.x;
    const int Me = sh ? T_ : g_cnt[z];
    const int m0 = blockIdx.y * 128;
    if (m0 >= Me) return;
    const int n0 = xt * 64;
    const int N = sh ? HS_ : H_;

    extern __shared__ char smem[];
    const uint32_t sb = smem_u32(smem);
    const int tid = threadIdx.x;

    const int ra = tid >> 1, sa = tid & 1;
    int ar = m0 + ra;
    if (!sh) ar = g_etok[z * T_ + (ar < Me ? ar : Me - 1)];
    const __half* aph = g_xh + (size_t)ar * D_;
    const int rb = tid >> 2, sbg = tid & 3;
    const size_t brow = sh ? (size_t)(n0 + rb) : ((size_t)z * H_ + n0 + rb);
    const __half* b1 = (sh ? g_ws1h : g_w1h) + brow * D_;
    const __half* b3 = (sh ? g_ws3h : g_w3h) + brow * D_;

    const uint32_t dA = sb + (uint32_t)ra * PITCH + (uint32_t)sa * 64;
    const uint32_t dB = sb + P1_AM + (uint32_t)rb * PITCH + (uint32_t)sbg * 32;

#define LOAD_GU(s, kt) do { \
        const int _ka = (kt) * 64 + sa * 32; \
        const int _kb = (kt) * 64 + sbg * 16; \
        const uint32_t _o = (uint32_t)(s) * P1_STG; \
        CPA(dA + _o,              aph + _ka); \
        CPA(dA + _o + 16,         aph + _ka + 8); \
        CPA(dA + _o + 32,         aph + _ka + 16); \
        CPA(dA + _o + 48,         aph + _ka + 24); \
        CPA(dB + _o,              b1 + _kb); \
        CPA(dB + _o + 16,         b1 + _kb + 8); \
        CPA(dB + _o + P1_BM,      b3 + _kb); \
        CPA(dB + _o + P1_BM + 16, b3 + _kb + 8); \
    } while (0)

    const int lane = tid & 31, wid = tid >> 5;
    const int wm = (wid & 1) * 64;
    const int wn = (wid >> 1) * 16;
    const uint32_t a_rowoff = (uint32_t)(wm + (lane & 15)) * PITCH + (uint32_t)(lane >> 4) * 16;
    const uint32_t b_rowoff = (uint32_t)(wn + ((lane >> 4) & 1) * 8 + (lane & 7)) * PITCH
                            + (uint32_t)((lane >> 3) & 1) * 16;

    float acc1[4][2][4], acc3[4][2][4];
#pragma unroll
    for (int i = 0; i < 4; i++)
#pragma unroll
        for (int j = 0; j < 2; j++)
#pragma unroll
            for (int q = 0; q < 4; q++) { acc1[i][j][q] = 0.f; acc3[i][j][q] = 0.f; }

    const int KT = D_ / 64;   // 16
    LOAD_GU(0, 0); CPC();

    for (int kt = 0; kt < KT; kt++) {
        CPW(0);
        __syncthreads();
        if (kt + 1 < KT) { LOAD_GU((kt + 1) & 1, kt + 1); CPC(); }
        const uint32_t base = sb + (uint32_t)(kt & 1) * P1_STG;
#pragma unroll
        for (int kk = 0; kk < 4; kk++) {
            const uint32_t kb = (uint32_t)kk * 32;
            uint32_t ah[4][4];
#pragma unroll
            for (int mf = 0; mf < 4; mf++)
                LDSM4(ah[mf], base + a_rowoff + (uint32_t)mf * (16 * PITCH) + kb);
            uint32_t b1f[4], b3f[4];
            LDSM4(b1f, base + P1_AM + b_rowoff + kb);
            LDSM4(b3f, base + P1_AM + P1_BM + b_rowoff + kb);
#pragma unroll
            for (int mf = 0; mf < 4; mf++) {
#pragma unroll
                for (int nf = 0; nf < 2; nf++) {
                    mma16816(acc1[mf][nf], ah[mf], &b1f[nf * 2]);
                    mma16816(acc3[mf][nf], ah[mf], &b3f[nf * 2]);
                }
            }
        }
    }
#undef LOAD_GU

    __half* OH = sh ? g_ssh : g_hth;
    const size_t rowBase = sh ? 0 : (size_t)z * T_;
#pragma unroll
    for (int mf = 0; mf < 4; mf++) {
#pragma unroll
        for (int nf = 0; nf < 2; nf++) {
            const int rr = wm + mf * 16 + (lane >> 2);
            const int cc = n0 + wn + nf * 8 + (lane & 3) * 2;
            float s0 = silu_(acc1[mf][nf][0]) * acc3[mf][nf][0];
            float s1 = silu_(acc1[mf][nf][1]) * acc3[mf][nf][1];
            float s2 = silu_(acc1[mf][nf][2]) * acc3[mf][nf][2];
            float s3 = silu_(acc1[mf][nf][3]) * acc3[mf][nf][3];
            const size_t o0 = (rowBase + m0 + rr) * (size_t)N + cc;
            const size_t o1 = (rowBase + m0 + rr + 8) * (size_t)N + cc;
            *(__half2*)(OH + o0) = __halves2half2(__float2half_rn(s0), __float2half_rn(s1));
            *(__half2*)(OH + o1) = __halves2half2(__float2half_rn(s2), __float2half_rn(s3));
        }
    }
}

// ================= phase 2: down proj, fp16, k64 =============
#define P2_AM (128 * PITCH)              // 18432
#define P2_STG (2 * P2_AM)               // 36864
#define P2_SMEM (2 * P2_STG)             // 73728

__global__ __launch_bounds__(256, 2) void gemm_dn(float* __restrict__ outp) {
    const int z = blockIdx.z;
    const bool sh = (z == E_);
    const int Me = sh ? T_ : g_cnt[z];
    const int m0 = blockIdx.y * 128;
    if (m0 >= Me) return;
    const int n0 = blockIdx.x * 128;
    const int Kd = sh ? HS_ : H_;

    extern __shared__ char smem[];
    const uint32_t sb = smem_u32(smem);
    const int tid = threadIdx.x;

    const int ra = tid >> 1, sa = tid & 1;
    const size_t arow = sh ? (size_t)(m0 + ra) : ((size_t)z * T_ + m0 + ra);
    const __half* aph = (sh ? g_ssh : g_hth) + arow * Kd;
    const size_t browk = sh ? (size_t)(n0 + ra) : ((size_t)z * D_ + n0 + ra);
    const __half* bp = (sh ? g_ws2h : g_w2h) + browk * Kd;

    const uint32_t dA = sb + (uint32_t)ra * PITCH + (uint32_t)sa * 64;
    const uint32_t dB = sb + P2_AM + (uint32_t)ra * PITCH + (uint32_t)sa * 64;

#define LOAD_DN(s, kt) do { \
        const int _k = (kt) * 64 + sa * 32; \
        const uint32_t _o = (uint32_t)(s) * P2_STG; \
        CPA(dA + _o,      aph + _k); \
        CPA(dA + _o + 16, aph + _k + 8); \
        CPA(dA + _o + 32, aph + _k + 16); \
        CPA(dA + _o + 48, aph + _k + 24); \
        CPA(dB + _o,      bp + _k); \
        CPA(dB + _o + 16, bp + _k + 8); \
        CPA(dB + _o + 32, bp + _k + 16); \
        CPA(dB + _o + 48, bp + _k + 24); \
    } while (0)

    const int lane = tid & 31, wid = tid >> 5;
    const int wm = (wid & 1) * 64;
    const int wn = (wid >> 1) * 32;
    const uint32_t a_rowoff = (uint32_t)(wm + (lane & 15)) * PITCH + (uint32_t)(lane >> 4) * 16;
    const uint32_t b_rowoff = (uint32_t)(wn + ((lane >> 4) & 1) * 8 + (lane & 7)) * PITCH
                            + (uint32_t)((lane >> 3) & 1) * 16;

    float acc[4][4][4];
#pragma unroll
    for (int i = 0; i < 4; i++)
#pragma unroll
        for (int j = 0; j < 4; j++)
#pragma unroll
            for (int q = 0; q < 4; q++) acc[i][j][q] = 0.f;

    const int KT = Kd / 64;   // 11 or 22
    LOAD_DN(0, 0); CPC();

    for (int kt = 0; kt < KT; kt++) {
        CPW(0);
        __syncthreads();
        if (kt + 1 < KT) { LOAD_DN((kt + 1) & 1, kt + 1); CPC(); }
        const uint32_t base = sb + (uint32_t)(kt & 1) * P2_STG;
#pragma unroll
        for (int kk = 0; kk < 4; kk++) {
            const uint32_t kb = (uint32_t)kk * 32;
            uint32_t ah[4][4];
#pragma unroll
            for (int mf = 0; mf < 4; mf++)
                LDSM4(ah[mf], base + a_rowoff + (uint32_t)mf * (16 * PITCH) + kb);
            uint32_t bf_[2][4];
#pragma unroll
            for (int p = 0; p < 2; p++)
                LDSM4(bf_[p], base + P2_AM + b_rowoff + (uint32_t)p * (16 * PITCH) + kb);
#pragma unroll
            for (int mf = 0; mf < 4; mf++) {
#pragma unroll
                for (int nf = 0; nf < 4; nf++) {
                    mma16816(acc[mf][nf], ah[mf], &bf_[nf >> 1][(nf & 1) * 2]);
                }
            }
        }
    }
#undef LOAD_DN

    if (sh) {
#pragma unroll
        for (int mf = 0; mf < 4; mf++) {
#pragma unroll
            for (int nf = 0; nf < 4; nf++) {
                const int rr = m0 + wm + mf * 16 + (lane >> 2);
                const int cc = n0 + wn + nf * 8 + (lane & 3) * 2;
                *(float2*)(outp + (size_t)rr * D_ + cc)       = make_float2(acc[mf][nf][0], acc[mf][nf][1]);
                *(float2*)(outp + (size_t)(rr + 8) * D_ + cc) = make_float2(acc[mf][nf][2], acc[mf][nf][3]);
            }
        }
    } else {
        __half* P = g_poh + (size_t)z * T_ * D_;
#pragma unroll
        for (int mf = 0; mf < 4; mf++) {
#pragma unroll
            for (int nf = 0; nf < 4; nf++) {
                const int rr = m0 + wm + mf * 16 + (lane >> 2);
                const int cc = n0 + wn + nf * 8 + (lane & 3) * 2;
                *(__half2*)(P + (size_t)rr * D_ + cc) =
                    __halves2half2(__float2half_rn(acc[mf][nf][0]), __float2half_rn(acc[mf][nf][1]));
                *(__half2*)(P + (size_t)(rr + 8) * D_ + cc) =
                    __halves2half2(__float2half_rn(acc[mf][nf][2]), __float2half_rn(acc[mf][nf][3]));
            }
        }
    }
}

// ---------------- combine: out += sum_k w_k * fp16 pair_out[slot_k] ------------
__global__ void combine_kernel(float* __restrict__ out) {
    int t = blockIdx.x;
    int c = threadIdx.x;   // 0..255, 4 floats each
    float4 a = ((float4*)out)[(size_t)t * (D_ / 4) + c];
#pragma unroll
    for (int k = 0; k < KSEL; k++) {
        int s = g_slot[t * KSEL + k];
        float wk = g_wt[t * KSEL + k];
        const __half2* P = (const __half2*)g_poh + (size_t)s * (D_ / 2) + c * 2;
        float2 v0 = __half22float2(P[0]);
        float2 v1 = __half22float2(P[1]);
        a.x += wk * v0.x; a.y += wk * v0.y; a.z += wk * v1.x; a.w += wk * v1.y;
    }
    ((float4*)out)[(size_t)t * (D_ / 4) + c] = a;
}

// ---------------- launch ----------------
#define SYMA(p, s) cudaGetSymbolAddress((void**)&p, s)

extern "C" void kernel_launch(void* const* d_in, const int* in_sizes, int n_in,
                              void* d_out, int out_size) {
    (void)in_sizes; (void)n_in; (void)out_size;
    const float* x   = (const float*)d_in[0];
    const float* gw  = (const float*)d_in[1];
    const float* gb  = (const float*)d_in[2];
    const float* w1  = (const float*)d_in[3];
    const float* w3  = (const float*)d_in[4];
    const float* w2  = (const float*)d_in[5];
    const float* ws1 = (const float*)d_in[6];
    const float* ws3 = (const float*)d_in[7];
    const float* ws2 = (const float*)d_in[8];
    float* out = (float*)d_out;

    cudaFuncSetAttribute(gemm_gu, cudaFuncAttributeMaxDynamicSharedMemorySize, P1_SMEM);
    cudaFuncSetAttribute(gemm_dn, cudaFuncAttributeMaxDynamicSharedMemorySize, P2_SMEM);
    cudaFuncSetAttribute(gate_kernel, cudaFuncAttributeMaxDynamicSharedMemorySize, GATE_SMEM);

    __half *xh, *w1h, *w3h, *w2h, *ws1h, *ws3h, *ws2h;
    SYMA(xh, g_xh);
    SYMA(w1h, g_w1h);   SYMA(w3h, g_w3h);   SYMA(w2h, g_w2h);
    SYMA(ws1h, g_ws1h); SYMA(ws3h, g_ws3h); SYMA(ws2h, g_ws2h);

    // 1: x -> fp16 (and zero expert counts)
    {
        size_t n16 = (size_t)T_ * D_ / 16;
        conv_x_kernel<<<(unsigned)((n16 + 255) / 256), 256>>>(x, xh, n16);
    }
    // 2: big weights (w1, w3, w2), 32 elems/thread
    {
        size_t n32 = (size_t)E_ * H_ * D_ / 32;
        conv_w3_kernel<<<dim3((unsigned)((n32 + 255) / 256), 3), 256>>>(
            w1, w3, w2, w1h, w3h, w2h, n32);
    }
    // 3: shared weights (ws1, ws3, ws2)
    {
        size_t n32 = (size_t)HS_ * D_ / 32;
        conv_w3_kernel<<<dim3((unsigned)((n32 + 255) / 256), 3), 256>>>(
            ws1, ws3, ws2, ws1h, ws3h, ws2h, n32);
    }

    // 4: gate (split-D: 2 warps/token, 8 tokens/block, 256 blocks)
    gate_kernel<<<T_ / 8, 512, GATE_SMEM>>>(x, gw, gb);

    // 5: phase 1 — gate+up+swiglu; routed z<16, shared folded into z=16,17
    gemm_gu<<<dim3(11, T_ / 128, 18), 256, P1_SMEM>>>();
    // 6: phase 2 — down proj
    gemm_dn<<<dim3(D_ / 128, T_ / 128, E_ + 1), 256, P2_SMEM>>>(out);

    combine_kernel<<<T_, 256>>>(out);             // 7
}

// round 16
// speedup vs baseline: 1.0333x; 1.0333x over previous
#include <cuda_runtime.h>
#include <cuda_fp16.h>
#include <float.h>
#include <math.h>
#include <cstdint>

#define T_   2048
#define D_   1024
#define H_   704
#define E_   16
#define HS_  1408
#define KSEL 4
#define ROUTE_SCALE_ 2.5446f

// ---------------- static device scratch ----------------
__device__ __half g_poh[(size_t)E_ * T_ * D_];   // routed down-proj (fp16)
__device__ int   g_cnt[E_];
__device__ int   g_etok[E_ * T_];
__device__ int   g_slot[T_ * KSEL];
__device__ float g_wt[T_ * KSEL];

__device__ __half g_xh[(size_t)T_ * D_];
__device__ __half g_w1h[(size_t)E_ * H_ * D_];
__device__ __half g_w3h[(size_t)E_ * H_ * D_];
__device__ __half g_w2h[(size_t)E_ * D_ * H_];
__device__ __half g_ws1h[(size_t)HS_ * D_];
__device__ __half g_ws3h[(size_t)HS_ * D_];
__device__ __half g_ws2h[(size_t)D_ * HS_];
__device__ __half g_hth[(size_t)E_ * T_ * H_];
__device__ __half g_ssh[(size_t)T_ * HS_];

// ---------------- helpers ----------------
__device__ __forceinline__ uint32_t smem_u32(const void* p) {
    uint32_t a;
    asm("{ .reg .u64 t; cvta.to.shared.u64 t, %1; cvt.u32.u64 %0, t; }" : "=r"(a) : "l"(p));
    return a;
}
#define CPA(dst, src) \
    asm volatile("cp.async.cg.shared.global [%0], [%1], 16;" :: "r"(dst), "l"(src))
#define CPC() asm volatile("cp.async.commit_group;" ::: "memory")
#define CPW(n) asm volatile("cp.async.wait_group %0;" :: "n"(n) : "memory")
#define LDSM4(R, addr) \
    asm volatile("ldmatrix.sync.aligned.m8n8.x4.shared.b16 {%0,%1,%2,%3}, [%4];" \
        : "=r"((R)[0]), "=r"((R)[1]), "=r"((R)[2]), "=r"((R)[3]) : "r"(addr))

__device__ __forceinline__ void mma16816(float* c, const uint32_t* a, const uint32_t* b) {
    asm volatile(
        "mma.sync.aligned.m16n8k16.row.col.f32.f16.f16.f32 "
        "{%0,%1,%2,%3}, {%4,%5,%6,%7}, {%8,%9}, {%0,%1,%2,%3};"
        : "+f"(c[0]), "+f"(c[1]), "+f"(c[2]), "+f"(c[3])
        : "r"(a[0]), "r"(a[1]), "r"(a[2]), "r"(a[3]), "r"(b[0]), "r"(b[1]));
}
__device__ __forceinline__ float silu_(float v) { return v / (1.f + expf(-v)); }

// ---------------- conversions (16 elems / thread) ----------------
__global__ void conv_x_kernel(const float* __restrict__ in,
                              __half* __restrict__ hi, size_t n16) {
    if (blockIdx.x == 0 && threadIdx.x < E_) g_cnt[threadIdx.x] = 0;
    size_t i = (size_t)blockIdx.x * blockDim.x + threadIdx.x;
    if (i >= n16) return;
    float4 v[4];
#pragma unroll
    for (int q = 0; q < 4; q++) v[q] = ((const float4*)in)[4 * i + q];
    __half h[16];
#pragma unroll
    for (int q = 0; q < 4; q++) {
        h[4 * q + 0] = __float2half_rn(v[q].x);
        h[4 * q + 1] = __float2half_rn(v[q].y);
        h[4 * q + 2] = __float2half_rn(v[q].z);
        h[4 * q + 3] = __float2half_rn(v[q].w);
    }
    ((uint4*)hi)[2 * i]     = ((uint4*)h)[0];
    ((uint4*)hi)[2 * i + 1] = ((uint4*)h)[1];
}

__global__ void conv_w3_kernel(const float* __restrict__ s0, const float* __restrict__ s1,
                               const float* __restrict__ s2,
                               __half* __restrict__ d0, __half* __restrict__ d1,
                               __half* __restrict__ d2, size_t n16) {
    size_t i = (size_t)blockIdx.x * blockDim.x + threadIdx.x;
    if (i >= n16) return;
    const int w = blockIdx.y;
    const float* in = (w == 0) ? s0 : ((w == 1) ? s1 : s2);
    __half* outp = (w == 0) ? d0 : ((w == 1) ? d1 : d2);
    float4 v[4];
#pragma unroll
    for (int q = 0; q < 4; q++) v[q] = ((const float4*)in)[4 * i + q];
    __half h[16];
#pragma unroll
    for (int q = 0; q < 4; q++) {
        h[4 * q + 0] = __float2half_rn(v[q].x);
        h[4 * q + 1] = __float2half_rn(v[q].y);
        h[4 * q + 2] = __float2half_rn(v[q].z);
        h[4 * q + 3] = __float2half_rn(v[q].w);
    }
    ((uint4*)outp)[2 * i]     = ((uint4*)h)[0];
    ((uint4*)outp)[2 * i + 1] = ((uint4*)h)[1];
}

// ---------------- gate: gw staged in smem, 1 token per warp, 512 threads -------
// 128 blocks x 512 threads; 16 tokens per block. (R12 configuration — best measured.)
#define GATE_SMEM (E_ * D_ * 4)   // 64 KB

__global__ __launch_bounds__(512) void gate_kernel(const float* __restrict__ x,
                                                   const float* __restrict__ gw,
                                                   const float* __restrict__ gb) {
    extern __shared__ float gws[];           // [E_][D_]
    const int tid = threadIdx.x;
    for (int i = tid; i < E_ * D_ / 4; i += 512)
        ((float4*)gws)[i] = ((const float4*)gw)[i];
    __syncthreads();

    const int warp = tid >> 5, lane = tid & 31;
    const int t = blockIdx.x * 16 + warp;
    const float4* xr = (const float4*)(x + (size_t)t * D_);
    float acc[E_];
#pragma unroll
    for (int e = 0; e < E_; e++) acc[e] = 0.f;
    for (int i = lane; i < D_ / 4; i += 32) {
        float4 xv = xr[i];
#pragma unroll
        for (int e = 0; e < E_; e++) {
            float4 g = ((const float4*)(gws + e * D_))[i];
            acc[e] += xv.x * g.x + xv.y * g.y + xv.z * g.z + xv.w * g.w;
        }
    }
#pragma unroll
    for (int e = 0; e < E_; e++) {
#pragma unroll
        for (int o = 16; o; o >>= 1)
            acc[e] += __shfl_xor_sync(0xffffffffu, acc[e], o);
    }

    if (lane == 0) {
        float sc[E_], r[E_];
#pragma unroll
        for (int e = 0; e < E_; e++) {
            sc[e] = 1.f / (1.f + expf(-acc[e]));
            r[e]  = sc[e] + gb[e];
        }
        float gs[4];
#pragma unroll
        for (int g = 0; g < 4; g++) {
            float m1 = -FLT_MAX, m2 = -FLT_MAX;
#pragma unroll
            for (int j = 0; j < 4; j++) {
                float v = r[4 * g + j];
                if (v > m1) { m2 = m1; m1 = v; }
                else if (v > m2) { m2 = v; }
            }
            gs[g] = m1 + m2;
        }
        int g1 = 0;
#pragma unroll
        for (int g = 1; g < 4; g++) if (gs[g] > gs[g1]) g1 = g;
        int g2 = -1;
#pragma unroll
        for (int g = 0; g < 4; g++) {
            if (g == g1) continue;
            if (g2 < 0 || gs[g] > gs[g2]) g2 = g;
        }
#pragma unroll
        for (int e = 0; e < E_; e++) {
            int g = e >> 2;
            if (g != g1 && g != g2) r[e] = -FLT_MAX;
        }
        int idx[KSEL];
        float wsum = 0.f;
#pragma unroll
        for (int k = 0; k < KSEL; k++) {
            int b = 0; float bv = -FLT_MAX;
#pragma unroll
            for (int e = 0; e < E_; e++)
                if (r[e] > bv) { bv = r[e]; b = e; }
            idx[k] = b;
            r[b] = -FLT_MAX;
            wsum += sc[b];
        }
        wsum = fmaxf(wsum, 1e-9f);
#pragma unroll
        for (int k = 0; k < KSEL; k++) {
            int e = idx[k];
            float wk = sc[e] / wsum * ROUTE_SCALE_;
            int pos = atomicAdd(&g_cnt[e], 1);
            g_etok[e * T_ + pos] = t;
            g_slot[t * KSEL + k] = e * T_ + pos;
            g_wt[t * KSEL + k]   = wk;
        }
    }
}

// ================= phase 1: dual GEMM (gate & up) + SwiGLU, fp16, k64 ==========
#define PITCH 144
#define P1_AM (128 * PITCH)             // 18432
#define P1_BM (64 * PITCH)              // 9216
#define P1_STG (P1_AM + 2 * P1_BM)      // 36864
#define P1_SMEM (2 * P1_STG)            // 73728

__global__ __launch_bounds__(256, 2) void gemm_gu() {
    const int z = blockIdx.z;
    const bool sh = (z >= E_);
    const int xt = sh ? ((z - E_) * 11 + blockIdx.x) : blockIdx.x;
    const int Me = sh ? T_ : g_cnt[z];
    const int m0 = blockIdx.y * 128;
    if (m0 >= Me) return;
    const int n0 = xt * 64;
    const int N = sh ? HS_ : H_;

    extern __shared__ char smem[];
    const uint32_t sb = smem_u32(smem);
    const int tid = threadIdx.x;

    const int ra = tid >> 1, sa = tid & 1;
    int ar = m0 + ra;
    if (!sh) ar = g_etok[z * T_ + (ar < Me ? ar : Me - 1)];
    const __half* aph = g_xh + (size_t)ar * D_;
    const int rb = tid >> 2, sbg = tid & 3;
    const size_t brow = sh ? (size_t)(n0 + rb) : ((size_t)z * H_ + n0 + rb);
    const __half* b1 = (sh ? g_ws1h : g_w1h) + brow * D_;
    const __half* b3 = (sh ? g_ws3h : g_w3h) + brow * D_;

    const uint32_t dA = sb + (uint32_t)ra * PITCH + (uint32_t)sa * 64;
    const uint32_t dB = sb + P1_AM + (uint32_t)rb * PITCH + (uint32_t)sbg * 32;

#define LOAD_GU(s, kt) do { \
        const int _ka = (kt) * 64 + sa * 32; \
        const int _kb = (kt) * 64 + sbg * 16; \
        const uint32_t _o = (uint32_t)(s) * P1_STG; \
        CPA(dA + _o,              aph + _ka); \
        CPA(dA + _o + 16,         aph + _ka + 8); \
        CPA(dA + _o + 32,         aph + _ka + 16); \
        CPA(dA + _o + 48,         aph + _ka + 24); \
        CPA(dB + _o,              b1 + _kb); \
        CPA(dB + _o + 16,         b1 + _kb + 8); \
        CPA(dB + _o + P1_BM,      b3 + _kb); \
        CPA(dB + _o + P1_BM + 16, b3 + _kb + 8); \
    } while (0)

    const int lane = tid & 31, wid = tid >> 5;
    const int wm = (wid & 1) * 64;
    const int wn = (wid >> 1) * 16;
    const uint32_t a_rowoff = (uint32_t)(wm + (lane & 15)) * PITCH + (uint32_t)(lane >> 4) * 16;
    const uint32_t b_rowoff = (uint32_t)(wn + ((lane >> 4) & 1) * 8 + (lane & 7)) * PITCH
                            + (uint32_t)((lane >> 3) & 1) * 16;

    float acc1[4][2][4], acc3[4][2][4];
#pragma unroll
    for (int i = 0; i < 4; i++)
#pragma unroll
        for (int j = 0; j < 2; j++)
#pragma unroll
            for (int q = 0; q < 4; q++) { acc1[i][j][q] = 0.f; acc3[i][j][q] = 0.f; }

    const int KT = D_ / 64;   // 16
    LOAD_GU(0, 0); CPC();

    for (int kt = 0; kt < KT; kt++) {
        CPW(0);
        __syncthreads();
        if (kt + 1 < KT) { LOAD_GU((kt + 1) & 1, kt + 1); CPC(); }
        const uint32_t base = sb + (uint32_t)(kt & 1) * P1_STG;
#pragma unroll
        for (int kk = 0; kk < 4; kk++) {
            const uint32_t kb = (uint32_t)kk * 32;
            uint32_t ah[4][4];
#pragma unroll
            for (int mf = 0; mf < 4; mf++)
                LDSM4(ah[mf], base + a_rowoff + (uint32_t)mf * (16 * PITCH) + kb);
            uint32_t b1f[4], b3f[4];
            LDSM4(b1f, base + P1_AM + b_rowoff + kb);
            LDSM4(b3f, base + P1_AM + P1_BM + b_rowoff + kb);
#pragma unroll
            for (int mf = 0; mf < 4; mf++) {
#pragma unroll
                for (int nf = 0; nf < 2; nf++) {
                    mma16816(acc1[mf][nf], ah[mf], &b1f[nf * 2]);
                    mma16816(acc3[mf][nf], ah[mf], &b3f[nf * 2]);
                }
            }
        }
    }
#undef LOAD_GU

    __half* OH = sh ? g_ssh : g_hth;
    const size_t rowBase = sh ? 0 : (size_t)z * T_;
#pragma unroll
    for (int mf = 0; mf < 4; mf++) {
#pragma unroll
        for (int nf = 0; nf < 2; nf++) {
            const int rr = wm + mf * 16 + (lane >> 2);
            const int cc = n0 + wn + nf * 8 + (lane & 3) * 2;
            float s0 = silu_(acc1[mf][nf][0]) * acc3[mf][nf][0];
            float s1 = silu_(acc1[mf][nf][1]) * acc3[mf][nf][1];
            float s2 = silu_(acc1[mf][nf][2]) * acc3[mf][nf][2];
            float s3 = silu_(acc1[mf][nf][3]) * acc3[mf][nf][3];
            const size_t o0 = (rowBase + m0 + rr) * (size_t)N + cc;
            const size_t o1 = (rowBase + m0 + rr + 8) * (size_t)N + cc;
            *(__half2*)(OH + o0) = __halves2half2(__float2half_rn(s0), __float2half_rn(s1));
            *(__half2*)(OH + o1) = __halves2half2(__float2half_rn(s2), __float2half_rn(s3));
        }
    }
}

// ================= phase 2: down proj, fp16, k64 =============
#define P2_AM (128 * PITCH)              // 18432
#define P2_STG (2 * P2_AM)               // 36864
#define P2_SMEM (2 * P2_STG)             // 73728

__global__ __launch_bounds__(256, 2) void gemm_dn(float* __restrict__ outp) {
    const int z = blockIdx.z;
    const bool sh = (z == E_);
    const int Me = sh ? T_ : g_cnt[z];
    const int m0 = blockIdx.y * 128;
    if (m0 >= Me) return;
    const int n0 = blockIdx.x * 128;
    const int Kd = sh ? HS_ : H_;

    extern __shared__ char smem[];
    const uint32_t sb = smem_u32(smem);
    const int tid = threadIdx.x;

    const int ra = tid >> 1, sa = tid & 1;
    const size_t arow = sh ? (size_t)(m0 + ra) : ((size_t)z * T_ + m0 + ra);
    const __half* aph = (sh ? g_ssh : g_hth) + arow * Kd;
    const size_t browk = sh ? (size_t)(n0 + ra) : ((size_t)z * D_ + n0 + ra);
    const __half* bp = (sh ? g_ws2h : g_w2h) + browk * Kd;

    const uint32_t dA = sb + (uint32_t)ra * PITCH + (uint32_t)sa * 64;
    const uint32_t dB = sb + P2_AM + (uint32_t)ra * PITCH + (uint32_t)sa * 64;

#define LOAD_DN(s, kt) do { \
        const int _k = (kt) * 64 + sa * 32; \
        const uint32_t _o = (uint32_t)(s) * P2_STG; \
        CPA(dA + _o,      aph + _k); \
        CPA(dA + _o + 16, aph + _k + 8); \
        CPA(dA + _o + 32, aph + _k + 16); \
        CPA(dA + _o + 48, aph + _k + 24); \
        CPA(dB + _o,      bp + _k); \
        CPA(dB + _o + 16, bp + _k + 8); \
        CPA(dB + _o + 32, bp + _k + 16); \
        CPA(dB + _o + 48, bp + _k + 24); \
    } while (0)

    const int lane = tid & 31, wid = tid >> 5;
    const int wm = (wid & 1) * 64;
    const int wn = (wid >> 1) * 32;
    const uint32_t a_rowoff = (uint32_t)(wm + (lane & 15)) * PITCH + (uint32_t)(lane >> 4) * 16;
    const uint32_t b_rowoff = (uint32_t)(wn + ((lane >> 4) & 1) * 8 + (lane & 7)) * PITCH
                            + (uint32_t)((lane >> 3) & 1) * 16;

    float acc[4][4][4];
#pragma unroll
    for (int i = 0; i < 4; i++)
#pragma unroll
        for (int j = 0; j < 4; j++)
#pragma unroll
            for (int q = 0; q < 4; q++) acc[i][j][q] = 0.f;

    const int KT = Kd / 64;   // 11 or 22
    LOAD_DN(0, 0); CPC();

    for (int kt = 0; kt < KT; kt++) {
        CPW(0);
        __syncthreads();
        if (kt + 1 < KT) { LOAD_DN((kt + 1) & 1, kt + 1); CPC(); }
        const uint32_t base = sb + (uint32_t)(kt & 1) * P2_STG;
#pragma unroll
        for (int kk = 0; kk < 4; kk++) {
            const uint32_t kb = (uint32_t)kk * 32;
            uint32_t ah[4][4];
#pragma unroll
            for (int mf = 0; mf < 4; mf++)
                LDSM4(ah[mf], base + a_rowoff + (uint32_t)mf * (16 * PITCH) + kb);
            uint32_t bf_[2][4];
#pragma unroll
            for (int p = 0; p < 2; p++)
                LDSM4(bf_[p], base + P2_AM + b_rowoff + (uint32_t)p * (16 * PITCH) + kb);
#pragma unroll
            for (int mf = 0; mf < 4; mf++) {
#pragma unroll
                for (int nf = 0; nf < 4; nf++) {
                    mma16816(acc[mf][nf], ah[mf], &bf_[nf >> 1][(nf & 1) * 2]);
                }
            }
        }
    }
#undef LOAD_DN

    if (sh) {
#pragma unroll
        for (int mf = 0; mf < 4; mf++) {
#pragma unroll
            for (int nf = 0; nf < 4; nf++) {
                const int rr = m0 + wm + mf * 16 + (lane >> 2);
                const int cc = n0 + wn + nf * 8 + (lane & 3) * 2;
                *(float2*)(outp + (size_t)rr * D_ + cc)       = make_float2(acc[mf][nf][0], acc[mf][nf][1]);
                *(float2*)(outp + (size_t)(rr + 8) * D_ + cc) = make_float2(acc[mf][nf][2], acc[mf][nf][3]);
            }
        }
    } else {
        __half* P = g_poh + (size_t)z * T_ * D_;
#pragma unroll
        for (int mf = 0; mf < 4; mf++) {
#pragma unroll
            for (int nf = 0; nf < 4; nf++) {
                const int rr = m0 + wm + mf * 16 + (lane >> 2);
                const int cc = n0 + wn + nf * 8 + (lane & 3) * 2;
                *(__half2*)(P + (size_t)rr * D_ + cc) =
                    __halves2half2(__float2half_rn(acc[mf][nf][0]), __float2half_rn(acc[mf][nf][1]));
                *(__half2*)(P + (size_t)(rr + 8) * D_ + cc) =
                    __halves2half2(__float2half_rn(acc[mf][nf][2]), __float2half_rn(acc[mf][nf][3]));
            }
        }
    }
}

// ---------------- combine: out += sum_k w_k * fp16 pair_out[slot_k] ------------
__global__ void combine_kernel(float* __restrict__ out) {
    int t = blockIdx.x;
    int c = threadIdx.x;   // 0..255, 4 floats each
    float4 a = ((float4*)out)[(size_t)t * (D_ / 4) + c];
#pragma unroll
    for (int k = 0; k < KSEL; k++) {
        int s = g_slot[t * KSEL + k];
        float wk = g_wt[t * KSEL + k];
        const __half2* P = (const __half2*)g_poh + (size_t)s * (D_ / 2) + c * 2;
        float2 v0 = __half22float2(P[0]);
        float2 v1 = __half22float2(P[1]);
        a.x += wk * v0.x; a.y += wk * v0.y; a.z += wk * v1.x; a.w += wk * v1.y;
    }
    ((float4*)out)[(size_t)t * (D_ / 4) + c] = a;
}

// ---------------- launch ----------------
#define SYMA(p, s) cudaGetSymbolAddress((void**)&p, s)

extern "C" void kernel_launch(void* const* d_in, const int* in_sizes, int n_in,
                              void* d_out, int out_size) {
    (void)in_sizes; (void)n_in; (void)out_size;
    const float* x   = (const float*)d_in[0];
    const float* gw  = (const float*)d_in[1];
    const float* gb  = (const float*)d_in[2];
    const float* w1  = (const float*)d_in[3];
    const float* w3  = (const float*)d_in[4];
    const float* w2  = (const float*)d_in[5];
    const float* ws1 = (const float*)d_in[6];
    const float* ws3 = (const float*)d_in[7];
    const float* ws2 = (const float*)d_in[8];
    float* out = (float*)d_out;

    cudaFuncSetAttribute(gemm_gu, cudaFuncAttributeMaxDynamicSharedMemorySize, P1_SMEM);
    cudaFuncSetAttribute(gemm_dn, cudaFuncAttributeMaxDynamicSharedMemorySize, P2_SMEM);
    cudaFuncSetAttribute(gate_kernel, cudaFuncAttributeMaxDynamicSharedMemorySize, GATE_SMEM);

    __half *xh, *w1h, *w3h, *w2h, *ws1h, *ws3h, *ws2h;
    SYMA(xh, g_xh);
    SYMA(w1h, g_w1h);   SYMA(w3h, g_w3h);   SYMA(w2h, g_w2h);
    SYMA(ws1h, g_ws1h); SYMA(ws3h, g_ws3h); SYMA(ws2h, g_ws2h);

    // 1: x -> fp16 (and zero expert counts)
    {
        size_t n16 = (size_t)T_ * D_ / 16;
        conv_x_kernel<<<(unsigned)((n16 + 255) / 256), 256>>>(x, xh, n16);
    }
    // 2: big weights (w1, w3, w2), 16 elems/thread
    {
        size_t n16 = (size_t)E_ * H_ * D_ / 16;
        conv_w3_kernel<<<dim3((unsigned)((n16 + 255) / 256), 3), 256>>>(
            w1, w3, w2, w1h, w3h, w2h, n16);
    }
    // 3: shared weights (ws1, ws3, ws2)
    {
        size_t n16 = (size_t)HS_ * D_ / 16;
        conv_w3_kernel<<<dim3((unsigned)((n16 + 255) / 256), 3), 256>>>(
            ws1, ws3, ws2, ws1h, ws3h, ws2h, n16);
    }

    // 4: gate (R12 config: 1 token/warp, 16 tokens/block, 128 blocks)
    gate_kernel<<<T_ / 16, 512, GATE_SMEM>>>(x, gw, gb);

    // 5: phase 1 — gate+up+swiglu; routed z<16, shared folded into z=16,17
    gemm_gu<<<dim3(11, T_ / 128, 18), 256, P1_SMEM>>>();
    // 6: phase 2 — down proj
    gemm_dn<<<dim3(D_ / 128, T_ / 128, E_ + 1), 256, P2_SMEM>>>(out);

    combine_kernel<<<T_, 256>>>(out);             // 7
}

// round 17
// speedup vs baseline: 1.0755x; 1.0409x over previous
#include <cuda_runtime.h>
#include <cuda_fp16.h>
#include <float.h>
#include <math.h>
#include <cstdint>

#define T_   2048
#define D_   1024
#define H_   704
#define E_   16
#define HS_  1408
#define KSEL 4
#define ROUTE_SCALE_ 2.5446f

// ---------------- static device scratch ----------------
__device__ __half g_poh[(size_t)E_ * T_ * D_];   // routed down-proj (fp16)
__device__ int   g_cnt[E_];
__device__ int   g_etok[E_ * T_];
__device__ int   g_slot[T_ * KSEL];
__device__ float g_wt[T_ * KSEL];

__device__ __half g_xh[(size_t)T_ * D_];
__device__ __half g_w1h[(size_t)E_ * H_ * D_];
__device__ __half g_w3h[(size_t)E_ * H_ * D_];
__device__ __half g_w2h[(size_t)E_ * D_ * H_];
__device__ __half g_ws1h[(size_t)HS_ * D_];
__device__ __half g_ws3h[(size_t)HS_ * D_];
__device__ __half g_ws2h[(size_t)D_ * HS_];
__device__ __half g_hth[(size_t)E_ * T_ * H_];
__device__ __half g_ssh[(size_t)T_ * HS_];

// ---------------- helpers ----------------
__device__ __forceinline__ uint32_t smem_u32(const void* p) {
    uint32_t a;
    asm("{ .reg .u64 t; cvta.to.shared.u64 t, %1; cvt.u32.u64 %0, t; }" : "=r"(a) : "l"(p));
    return a;
}
#define CPA(dst, src) \
    asm volatile("cp.async.cg.shared.global [%0], [%1], 16;" :: "r"(dst), "l"(src))
#define CPC() asm volatile("cp.async.commit_group;" ::: "memory")
#define CPW(n) asm volatile("cp.async.wait_group %0;" :: "n"(n) : "memory")
#define LDSM4(R, addr) \
    asm volatile("ldmatrix.sync.aligned.m8n8.x4.shared.b16 {%0,%1,%2,%3}, [%4];" \
        : "=r"((R)[0]), "=r"((R)[1]), "=r"((R)[2]), "=r"((R)[3]) : "r"(addr))

__device__ __forceinline__ void mma16816(float* c, const uint32_t* a, const uint32_t* b) {
    asm volatile(
        "mma.sync.aligned.m16n8k16.row.col.f32.f16.f16.f32 "
        "{%0,%1,%2,%3}, {%4,%5,%6,%7}, {%8,%9}, {%0,%1,%2,%3};"
        : "+f"(c[0]), "+f"(c[1]), "+f"(c[2]), "+f"(c[3])
        : "r"(a[0]), "r"(a[1]), "r"(a[2]), "r"(a[3]), "r"(b[0]), "r"(b[1]));
}
__device__ __forceinline__ float silu_(float v) { return v / (1.f + expf(-v)); }

// ---------------- conversions (16 elems / thread) ----------------
__global__ void conv_x_kernel(const float* __restrict__ in,
                              __half* __restrict__ hi, size_t n16) {
    if (blockIdx.x == 0 && threadIdx.x < E_) g_cnt[threadIdx.x] = 0;
    size_t i = (size_t)blockIdx.x * blockDim.x + threadIdx.x;
    if (i >= n16) return;
    float4 v[4];
#pragma unroll
    for (int q = 0; q < 4; q++) v[q] = ((const float4*)in)[4 * i + q];
    __half h[16];
#pragma unroll
    for (int q = 0; q < 4; q++) {
        h[4 * q + 0] = __float2half_rn(v[q].x);
        h[4 * q + 1] = __float2half_rn(v[q].y);
        h[4 * q + 2] = __float2half_rn(v[q].z);
        h[4 * q + 3] = __float2half_rn(v[q].w);
    }
    ((uint4*)hi)[2 * i]     = ((uint4*)h)[0];
    ((uint4*)hi)[2 * i + 1] = ((uint4*)h)[1];
}

__global__ void conv_w3_kernel(const float* __restrict__ s0, const float* __restrict__ s1,
                               const float* __restrict__ s2,
                               __half* __restrict__ d0, __half* __restrict__ d1,
                               __half* __restrict__ d2, size_t n16) {
    size_t i = (size_t)blockIdx.x * blockDim.x + threadIdx.x;
    if (i >= n16) return;
    const int w = blockIdx.y;
    const float* in = (w == 0) ? s0 : ((w == 1) ? s1 : s2);
    __half* outp = (w == 0) ? d0 : ((w == 1) ? d1 : d2);
    float4 v[4];
#pragma unroll
    for (int q = 0; q < 4; q++) v[q] = ((const float4*)in)[4 * i + q];
    __half h[16];
#pragma unroll
    for (int q = 0; q < 4; q++) {
        h[4 * q + 0] = __float2half_rn(v[q].x);
        h[4 * q + 1] = __float2half_rn(v[q].y);
        h[4 * q + 2] = __float2half_rn(v[q].z);
        h[4 * q + 3] = __float2half_rn(v[q].w);
    }
    ((uint4*)outp)[2 * i]     = ((uint4*)h)[0];
    ((uint4*)outp)[2 * i + 1] = ((uint4*)h)[1];
}

// ---------------- gate: gw staged in smem, 1 token per warp, 512 threads -------
#define GATE_SMEM (E_ * D_ * 4)   // 64 KB

__global__ __launch_bounds__(512) void gate_kernel(const float* __restrict__ x,
                                                   const float* __restrict__ gw,
                                                   const float* __restrict__ gb) {
    extern __shared__ float gws[];           // [E_][D_]
    const int tid = threadIdx.x;
    for (int i = tid; i < E_ * D_ / 4; i += 512)
        ((float4*)gws)[i] = ((const float4*)gw)[i];
    __syncthreads();

    const int warp = tid >> 5, lane = tid & 31;
    const int t = blockIdx.x * 16 + warp;
    const float4* xr = (const float4*)(x + (size_t)t * D_);
    float acc[E_];
#pragma unroll
    for (int e = 0; e < E_; e++) acc[e] = 0.f;
    for (int i = lane; i < D_ / 4; i += 32) {
        float4 xv = xr[i];
#pragma unroll
        for (int e = 0; e < E_; e++) {
            float4 g = ((const float4*)(gws + e * D_))[i];
            acc[e] += xv.x * g.x + xv.y * g.y + xv.z * g.z + xv.w * g.w;
        }
    }
#pragma unroll
    for (int e = 0; e < E_; e++) {
#pragma unroll
        for (int o = 16; o; o >>= 1)
            acc[e] += __shfl_xor_sync(0xffffffffu, acc[e], o);
    }

    if (lane == 0) {
        float sc[E_], r[E_];
#pragma unroll
        for (int e = 0; e < E_; e++) {
            sc[e] = 1.f / (1.f + expf(-acc[e]));
            r[e]  = sc[e] + gb[e];
        }
        float gs[4];
#pragma unroll
        for (int g = 0; g < 4; g++) {
            float m1 = -FLT_MAX, m2 = -FLT_MAX;
#pragma unroll
            for (int j = 0; j < 4; j++) {
                float v = r[4 * g + j];
                if (v > m1) { m2 = m1; m1 = v; }
                else if (v > m2) { m2 = v; }
            }
            gs[g] = m1 + m2;
        }
        int g1 = 0;
#pragma unroll
        for (int g = 1; g < 4; g++) if (gs[g] > gs[g1]) g1 = g;
        int g2 = -1;
#pragma unroll
        for (int g = 0; g < 4; g++) {
            if (g == g1) continue;
            if (g2 < 0 || gs[g] > gs[g2]) g2 = g;
        }
#pragma unroll
        for (int e = 0; e < E_; e++) {
            int g = e >> 2;
            if (g != g1 && g != g2) r[e] = -FLT_MAX;
        }
        int idx[KSEL];
        float wsum = 0.f;
#pragma unroll
        for (int k = 0; k < KSEL; k++) {
            int b = 0; float bv = -FLT_MAX;
#pragma unroll
            for (int e = 0; e < E_; e++)
                if (r[e] > bv) { bv = r[e]; b = e; }
            idx[k] = b;
            r[b] = -FLT_MAX;
            wsum += sc[b];
        }
        wsum = fmaxf(wsum, 1e-9f);
#pragma unroll
        for (int k = 0; k < KSEL; k++) {
            int e = idx[k];
            float wk = sc[e] / wsum * ROUTE_SCALE_;
            int pos = atomicAdd(&g_cnt[e], 1);
            g_etok[e * T_ + pos] = t;
            g_slot[t * KSEL + k] = e * T_ + pos;
            g_wt[t * KSEL + k]   = wk;
        }
    }
}

// ================= phase 1: dual GEMM (gate & up) + SwiGLU, fp16, k64 ==========
// Grid (11, 16, 18). z=0,1: shared slices (launch FIRST). z>=2: routed expert z-2.
#define PITCH 144
#define P1_AM (128 * PITCH)             // 18432
#define P1_BM (64 * PITCH)              // 9216
#define P1_STG (P1_AM + 2 * P1_BM)      // 36864
#define P1_SMEM (2 * P1_STG)            // 73728

__global__ __launch_bounds__(256, 2) void gemm_gu() {
    const int z = blockIdx.z;
    const bool sh = (z < 2);
    const int ez = z - 2;                 // routed expert index
    const int xt = sh ? (z * 11 + blockIdx.x) : blockIdx.x;
    const int Me = sh ? T_ : g_cnt[ez];
    const int m0 = blockIdx.y * 128;
    if (m0 >= Me) return;
    const int n0 = xt * 64;
    const int N = sh ? HS_ : H_;

    extern __shared__ char smem[];
    const uint32_t sb = smem_u32(smem);
    const int tid = threadIdx.x;

    const int ra = tid >> 1, sa = tid & 1;
    int ar = m0 + ra;
    if (!sh) ar = g_etok[ez * T_ + (ar < Me ? ar : Me - 1)];
    const __half* aph = g_xh + (size_t)ar * D_;
    const int rb = tid >> 2, sbg = tid & 3;
    const size_t brow = sh ? (size_t)(n0 + rb) : ((size_t)ez * H_ + n0 + rb);
    const __half* b1 = (sh ? g_ws1h : g_w1h) + brow * D_;
    const __half* b3 = (sh ? g_ws3h : g_w3h) + brow * D_;

    const uint32_t dA = sb + (uint32_t)ra * PITCH + (uint32_t)sa * 64;
    const uint32_t dB = sb + P1_AM + (uint32_t)rb * PITCH + (uint32_t)sbg * 32;

#define LOAD_GU(s, kt) do { \
        const int _ka = (kt) * 64 + sa * 32; \
        const int _kb = (kt) * 64 + sbg * 16; \
        const uint32_t _o = (uint32_t)(s) * P1_STG; \
        CPA(dA + _o,              aph + _ka); \
        CPA(dA + _o + 16,         aph + _ka + 8); \
        CPA(dA + _o + 32,         aph + _ka + 16); \
        CPA(dA + _o + 48,         aph + _ka + 24); \
        CPA(dB + _o,              b1 + _kb); \
        CPA(dB + _o + 16,         b1 + _kb + 8); \
        CPA(dB + _o + P1_BM,      b3 + _kb); \
        CPA(dB + _o + P1_BM + 16, b3 + _kb + 8); \
    } while (0)

    const int lane = tid & 31, wid = tid >> 5;
    const int wm = (wid & 1) * 64;
    const int wn = (wid >> 1) * 16;
    const uint32_t a_rowoff = (uint32_t)(wm + (lane & 15)) * PITCH + (uint32_t)(lane >> 4) * 16;
    const uint32_t b_rowoff = (uint32_t)(wn + ((lane >> 4) & 1) * 8 + (lane & 7)) * PITCH
                            + (uint32_t)((lane >> 3) & 1) * 16;

    float acc1[4][2][4], acc3[4][2][4];
#pragma unroll
    for (int i = 0; i < 4; i++)
#pragma unroll
        for (int j = 0; j < 2; j++)
#pragma unroll
            for (int q = 0; q < 4; q++) { acc1[i][j][q] = 0.f; acc3[i][j][q] = 0.f; }

    const int KT = D_ / 64;   // 16
    LOAD_GU(0, 0); CPC();

    for (int kt = 0; kt < KT; kt++) {
        CPW(0);
        __syncthreads();
        if (kt + 1 < KT) { LOAD_GU((kt + 1) & 1, kt + 1); CPC(); }
        const uint32_t base = sb + (uint32_t)(kt & 1) * P1_STG;
#pragma unroll
        for (int kk = 0; kk < 4; kk++) {
            const uint32_t kb = (uint32_t)kk * 32;
            uint32_t ah[4][4];
#pragma unroll
            for (int mf = 0; mf < 4; mf++)
                LDSM4(ah[mf], base + a_rowoff + (uint32_t)mf * (16 * PITCH) + kb);
            uint32_t b1f[4], b3f[4];
            LDSM4(b1f, base + P1_AM + b_rowoff + kb);
            LDSM4(b3f, base + P1_AM + P1_BM + b_rowoff + kb);
#pragma unroll
            for (int mf = 0; mf < 4; mf++) {
#pragma unroll
                for (int nf = 0; nf < 2; nf++) {
                    mma16816(acc1[mf][nf], ah[mf], &b1f[nf * 2]);
                    mma16816(acc3[mf][nf], ah[mf], &b3f[nf * 2]);
                }
            }
        }
    }
#undef LOAD_GU

    __half* OH = sh ? g_ssh : g_hth;
    const size_t rowBase = sh ? 0 : (size_t)ez * T_;
#pragma unroll
    for (int mf = 0; mf < 4; mf++) {
#pragma unroll
        for (int nf = 0; nf < 2; nf++) {
            const int rr = wm + mf * 16 + (lane >> 2);
            const int cc = n0 + wn + nf * 8 + (lane & 3) * 2;
            float s0 = silu_(acc1[mf][nf][0]) * acc3[mf][nf][0];
            float s1 = silu_(acc1[mf][nf][1]) * acc3[mf][nf][1];
            float s2 = silu_(acc1[mf][nf][2]) * acc3[mf][nf][2];
            float s3 = silu_(acc1[mf][nf][3]) * acc3[mf][nf][3];
            const size_t o0 = (rowBase + m0 + rr) * (size_t)N + cc;
            const size_t o1 = (rowBase + m0 + rr + 8) * (size_t)N + cc;
            *(__half2*)(OH + o0) = __halves2half2(__float2half_rn(s0), __float2half_rn(s1));
            *(__half2*)(OH + o1) = __halves2half2(__float2half_rn(s2), __float2half_rn(s3));
        }
    }
}

// ================= phase 2: down proj, fp16, k64 =============
// Grid (8, 16, 17). z=0: shared (K=1408, 2x duration — launch FIRST). z>=1: expert z-1.
#define P2_AM (128 * PITCH)              // 18432
#define P2_STG (2 * P2_AM)               // 36864
#define P2_SMEM (2 * P2_STG)             // 73728

__global__ __launch_bounds__(256, 2) void gemm_dn(float* __restrict__ outp) {
    const int z = blockIdx.z;
    const bool sh = (z == 0);
    const int ez = z - 1;
    const int Me = sh ? T_ : g_cnt[ez];
    const int m0 = blockIdx.y * 128;
    if (m0 >= Me) return;
    const int n0 = blockIdx.x * 128;
    const int Kd = sh ? HS_ : H_;

    extern __shared__ char smem[];
    const uint32_t sb = smem_u32(smem);
    const int tid = threadIdx.x;

    const int ra = tid >> 1, sa = tid & 1;
    const size_t arow = sh ? (size_t)(m0 + ra) : ((size_t)ez * T_ + m0 + ra);
    const __half* aph = (sh ? g_ssh : g_hth) + arow * Kd;
    const size_t browk = sh ? (size_t)(n0 + ra) : ((size_t)ez * D_ + n0 + ra);
    const __half* bp = (sh ? g_ws2h : g_w2h) + browk * Kd;

    const uint32_t dA = sb + (uint32_t)ra * PITCH + (uint32_t)sa * 64;
    const uint32_t dB = sb + P2_AM + (uint32_t)ra * PITCH + (uint32_t)sa * 64;

#define LOAD_DN(s, kt) do { \
        const int _k = (kt) * 64 + sa * 32; \
        const uint32_t _o = (uint32_t)(s) * P2_STG; \
        CPA(dA + _o,      aph + _k); \
        CPA(dA + _o + 16, aph + _k + 8); \
        CPA(dA + _o + 32, aph + _k + 16); \
        CPA(dA + _o + 48, aph + _k + 24); \
        CPA(dB + _o,      bp + _k); \
        CPA(dB + _o + 16, bp + _k + 8); \
        CPA(dB + _o + 32, bp + _k + 16); \
        CPA(dB + _o + 48, bp + _k + 24); \
    } while (0)

    const int lane = tid & 31, wid = tid >> 5;
    const int wm = (wid & 1) * 64;
    const int wn = (wid >> 1) * 32;
    const uint32_t a_rowoff = (uint32_t)(wm + (lane & 15)) * PITCH + (uint32_t)(lane >> 4) * 16;
    const uint32_t b_rowoff = (uint32_t)(wn + ((lane >> 4) & 1) * 8 + (lane & 7)) * PITCH
                            + (uint32_t)((lane >> 3) & 1) * 16;

    float acc[4][4][4];
#pragma unroll
    for (int i = 0; i < 4; i++)
#pragma unroll
        for (int j = 0; j < 4; j++)
#pragma unroll
            for (int q = 0; q < 4; q++) acc[i][j][q] = 0.f;

    const int KT = Kd / 64;   // 22 (shared) or 11 (routed)
    LOAD_DN(0, 0); CPC();

    for (int kt = 0; kt < KT; kt++) {
        CPW(0);
        __syncthreads();
        if (kt + 1 < KT) { LOAD_DN((kt + 1) & 1, kt + 1); CPC(); }
        const uint32_t base = sb + (uint32_t)(kt & 1) * P2_STG;
#pragma unroll
        for (int kk = 0; kk < 4; kk++) {
            const uint32_t kb = (uint32_t)kk * 32;
            uint32_t ah[4][4];
#pragma unroll
            for (int mf = 0; mf < 4; mf++)
                LDSM4(ah[mf], base + a_rowoff + (uint32_t)mf * (16 * PITCH) + kb);
            uint32_t bf_[2][4];
#pragma unroll
            for (int p = 0; p < 2; p++)
                LDSM4(bf_[p], base + P2_AM + b_rowoff + (uint32_t)p * (16 * PITCH) + kb);
#pragma unroll
            for (int mf = 0; mf < 4; mf++) {
#pragma unroll
                for (int nf = 0; nf < 4; nf++) {
                    mma16816(acc[mf][nf], ah[mf], &bf_[nf >> 1][(nf & 1) * 2]);
                }
            }
        }
    }
#undef LOAD_DN

    if (sh) {
#pragma unroll
        for (int mf = 0; mf < 4; mf++) {
#pragma unroll
            for (int nf = 0; nf < 4; nf++) {
                const int rr = m0 + wm + mf * 16 + (lane >> 2);
                const int cc = n0 + wn + nf * 8 + (lane & 3) * 2;
                *(float2*)(outp + (size_t)rr * D_ + cc)       = make_float2(acc[mf][nf][0], acc[mf][nf][1]);
                *(float2*)(outp + (size_t)(rr + 8) * D_ + cc) = make_float2(acc[mf][nf][2], acc[mf][nf][3]);
            }
        }
    } else {
        __half* P = g_poh + (size_t)ez * T_ * D_;
#pragma unroll
        for (int mf = 0; mf < 4; mf++) {
#pragma unroll
            for (int nf = 0; nf < 4; nf++) {
                const int rr = m0 + wm + mf * 16 + (lane >> 2);
                const int cc = n0 + wn + nf * 8 + (lane & 3) * 2;
                *(__half2*)(P + (size_t)rr * D_ + cc) =
                    __halves2half2(__float2half_rn(acc[mf][nf][0]), __float2half_rn(acc[mf][nf][1]));
                *(__half2*)(P + (size_t)(rr + 8) * D_ + cc) =
                    __halves2half2(__float2half_rn(acc[mf][nf][2]), __float2half_rn(acc[mf][nf][3]));
            }
        }
    }
}

// ---------------- combine: out += sum_k w_k * fp16 pair_out[slot_k] ------------
__global__ void combine_kernel(float* __restrict__ out) {
    int t = blockIdx.x;
    int c = threadIdx.x;   // 0..255, 4 floats each
    float4 a = ((float4*)out)[(size_t)t * (D_ / 4) + c];
#pragma unroll
    for (int k = 0; k < KSEL; k++) {
        int s = g_slot[t * KSEL + k];
        float wk = g_wt[t * KSEL + k];
        const __half2* P = (const __half2*)g_poh + (size_t)s * (D_ / 2) + c * 2;
        float2 v0 = __half22float2(P[0]);
        float2 v1 = __half22float2(P[1]);
        a.x += wk * v0.x; a.y += wk * v0.y; a.z += wk * v1.x; a.w += wk * v1.y;
    }
    ((float4*)out)[(size_t)t * (D_ / 4) + c] = a;
}

// ---------------- launch ----------------
#define SYMA(p, s) cudaGetSymbolAddress((void**)&p, s)

extern "C" void kernel_launch(void* const* d_in, const int* in_sizes, int n_in,
                              void* d_out, int out_size) {
    (void)in_sizes; (void)n_in; (void)out_size;
    const float* x   = (const float*)d_in[0];
    const float* gw  = (const float*)d_in[1];
    const float* gb  = (const float*)d_in[2];
    const float* w1  = (const float*)d_in[3];
    const float* w3  = (const float*)d_in[4];
    const float* w2  = (const float*)d_in[5];
    const float* ws1 = (const float*)d_in[6];
    const float* ws3 = (const float*)d_in[7];
    const float* ws2 = (const float*)d_in[8];
    float* out = (float*)d_out;

    cudaFuncSetAttribute(gemm_gu, cudaFuncAttributeMaxDynamicSharedMemorySize, P1_SMEM);
    cudaFuncSetAttribute(gemm_dn, cudaFuncAttributeMaxDynamicSharedMemorySize, P2_SMEM);
    cudaFuncSetAttribute(gate_kernel, cudaFuncAttributeMaxDynamicSharedMemorySize, GATE_SMEM);

    __half *xh, *w1h, *w3h, *w2h, *ws1h, *ws3h, *ws2h;
    SYMA(xh, g_xh);
    SYMA(w1h, g_w1h);   SYMA(w3h, g_w3h);   SYMA(w2h, g_w2h);
    SYMA(ws1h, g_ws1h); SYMA(ws3h, g_ws3h); SYMA(ws2h, g_ws2h);

    // 1: x -> fp16 (and zero expert counts)
    {
        size_t n16 = (size_t)T_ * D_ / 16;
        conv_x_kernel<<<(unsigned)((n16 + 255) / 256), 256>>>(x, xh, n16);
    }
    // 2: big weights (w1, w3, w2), 16 elems/thread
    {
        size_t n16 = (size_t)E_ * H_ * D_ / 16;
        conv_w3_kernel<<<dim3((unsigned)((n16 + 255) / 256), 3), 256>>>(
            w1, w3, w2, w1h, w3h, w2h, n16);
    }
    // 3: shared weights (ws1, ws3, ws2)
    {
        size_t n16 = (size_t)HS_ * D_ / 16;
        conv_w3_kernel<<<dim3((unsigned)((n16 + 255) / 256), 3), 256>>>(
            ws1, ws3, ws2, ws1h, ws3h, ws2h, n16);
    }

    // 4: gate (1 token/warp, 16 tokens/block, 128 blocks)
    gate_kernel<<<T_ / 16, 512, GATE_SMEM>>>(x, gw, gb);

    // 5: phase 1 — gate+up+swiglu; shared z=0,1 first, routed z=2..17
    gemm_gu<<<dim3(11, T_ / 128, 18), 256, P1_SMEM>>>();
    // 6: phase 2 — down proj; shared z=0 (longest CTAs) first, routed z=1..16
    gemm_dn<<<dim3(D_ / 128, T_ / 128, E_ + 1), 256, P2_SMEM>>>(out);

    combine_kernel<<<T_, 256>>>(out);             // 7
}